// round 10
// baseline (speedup 1.0000x reference)
#include <cuda_runtime.h>
#include <stdint.h>

constexpr int B  = 2;
constexpr int S  = 2048;
constexpr int D  = 1024;
constexpr int H  = 16;
constexpr int HD = 64;
constexpr int M  = B * S;   // 4096

// Scratch (device globals — no allocation allowed)
__device__ float g_q[(size_t)B * H * S * HD];
__device__ float g_k[(size_t)B * H * S * HD];
__device__ float g_v[(size_t)B * H * S * HD];
__device__ float g_attn[(size_t)B * S * D];
__device__ float g_xt[(size_t)M * D];          // tf32-rounded x
__device__ float g_wt[4 * (size_t)D * D];      // tf32-rounded Wq,Wk,Wv,Wp

__device__ __forceinline__ uint32_t f2tf(float f) {
    uint32_t u;
    asm("cvt.rna.tf32.f32 %0, %1;" : "=r"(u) : "f"(f));
    return u;
}
__device__ __forceinline__ float rndtf(float f) { return __uint_as_float(f2tf(f)); }

__device__ __forceinline__ void mma8(float* c,
                                     uint32_t a0, uint32_t a1, uint32_t a2, uint32_t a3,
                                     uint32_t b0, uint32_t b1) {
    asm volatile(
        "mma.sync.aligned.m16n8k8.row.col.f32.tf32.tf32.f32 "
        "{%0,%1,%2,%3},{%4,%5,%6,%7},{%8,%9},{%0,%1,%2,%3};"
        : "+f"(c[0]), "+f"(c[1]), "+f"(c[2]), "+f"(c[3])
        : "r"(a0), "r"(a1), "r"(a2), "r"(a3), "r"(b0), "r"(b1));
}

__device__ __forceinline__ uint4 ldsm4(uint32_t addr) {
    uint4 r;
    asm volatile("ldmatrix.sync.aligned.m8n8.x4.shared.b16 {%0,%1,%2,%3}, [%4];"
                 : "=r"(r.x), "=r"(r.y), "=r"(r.z), "=r"(r.w) : "r"(addr));
    return r;
}

__device__ __forceinline__ void cpa16(uint32_t dst, const void* src) {
    asm volatile("cp.async.cg.shared.global [%0], [%1], 16;" :: "r"(dst), "l"(src));
}
__device__ __forceinline__ void cpcommit() { asm volatile("cp.async.commit_group;"); }
template <int N>
__device__ __forceinline__ void cpwait() { asm volatile("cp.async.wait_group %0;" :: "n"(N)); }

// ---------------------------------------------------------------------------
// tf32 pre-round pass: x and the 4 weight matrices
// ---------------------------------------------------------------------------
__global__ __launch_bounds__(256)
void tf32_cvt(const float* __restrict__ x,  const float* __restrict__ wq,
              const float* __restrict__ wk, const float* __restrict__ wv,
              const float* __restrict__ wp,
              float* __restrict__ xo, float* __restrict__ qo,
              float* __restrict__ ko, float* __restrict__ vo, float* __restrict__ po)
{
    const float* s; float* d; int n;
    switch (blockIdx.y) {
        case 0: s = x;  d = xo; n = M * D; break;
        case 1: s = wq; d = qo; n = D * D; break;
        case 2: s = wk; d = ko; n = D * D; break;
        case 3: s = wv; d = vo; n = D * D; break;
        default: s = wp; d = po; n = D * D; break;
    }
    for (int i = (blockIdx.x * 256 + threadIdx.x) * 4; i < n; i += 512 * 256 * 4) {
        const float4 v = *(const float4*)(s + i);
        *(uint4*)(d + i) = make_uint4(f2tf(v.x), f2tf(v.y), f2tf(v.z), f2tf(v.w));
    }
}

// ---------------------------------------------------------------------------
// TF32 GEMM: C = A[M,1024] * W[1024,1024]^T + bias.  Inputs pre-rounded.
// Block 128x128, BK=16, 8 warps, warp tile 64x32. cp.async 4-stage pipeline
// (2 full stages in flight during compute). Smem stage s (16KB): A @ s*16384,
// B @ s*16384+8192; swizzle g^=((row>>1)&3).
// MODE 0: row-major fp32 out. MODE 2: QKV fused (z), tf32-rounded scatter
//         to [B,H,S,HD]; Q additionally scaled by 0.125.
// ---------------------------------------------------------------------------
template <int MODE>
__global__ __launch_bounds__(256, 2)
void gemm_tc(const float* __restrict__ A,
             const float* __restrict__ W0, const float* __restrict__ b0_,
             const float* __restrict__ W1, const float* __restrict__ b1_,
             const float* __restrict__ W2, const float* __restrict__ b2_,
             float* __restrict__ C0, float* __restrict__ C1, float* __restrict__ C2)
{
    constexpr int K = 1024;
    constexpr int N = 1024;
    constexpr int NKB = 64;

    const float* W; const float* bias; float* C; int z = 0;
    if (MODE != 2) { W = W0; bias = b0_; C = C0; }
    else {
        z    = blockIdx.z;
        W    = (z == 0) ? W0 : (z == 1) ? W1 : W2;
        bias = (z == 0) ? b0_ : (z == 1) ? b1_ : b2_;
        C    = (z == 0) ? C0 : (z == 1) ? C1 : C2;
    }

    extern __shared__ __align__(16) uint32_t smg[];
    const uint32_t sbase = (uint32_t)__cvta_generic_to_shared(smg);

    const int t    = threadIdx.x;
    const int lane = t & 31;
    const int warp = t >> 5;
    const int gid  = lane >> 2;
    const int tig  = lane & 3;
    const int wm   = warp >> 2;
    const int wn   = warp & 3;
    const int bm   = blockIdx.y * 128;
    const int bn   = blockIdx.x * 128;

    // cp.async staging
    const int srow = t >> 2;
    const int sg   = t & 3;
    const float* sa0 = A + (size_t)(bm + srow) * K + sg * 4;
    const float* sw0 = W + (size_t)(bn + srow) * K + sg * 4;
    const uint32_t dsw = (uint32_t)(srow * 64 + ((sg ^ ((srow >> 1) & 3)) << 4));

    // ldmatrix fragment addresses (byte offsets within a stage)
    uint32_t relA[4], relB[2];
    {
        const int hiA = (lane >> 4) & 1;
#pragma unroll
        for (int mt = 0; mt < 4; mt++) {
            const int row = wm * 64 + mt * 16 + (lane & 7) + (lane & 8);
            relA[mt] = row * 64 + (uint32_t)((hiA ^ ((row >> 1) & 3)) << 4);
        }
        const int hiB = (lane >> 3) & 1;
#pragma unroll
        for (int n2 = 0; n2 < 2; n2++) {
            const int row = wn * 32 + n2 * 16 + (lane & 7) + ((lane >> 1) & 8);
            relB[n2] = 8192u + row * 64 + (uint32_t)((hiB ^ ((row >> 1) & 3)) << 4);
        }
    }

#define GISSUE(kb, st)                                            \
    {                                                             \
        const uint32_t dd = sbase + (uint32_t)(st) * 16384u + dsw;\
        const float* a = sa0 + (kb) * 16;                         \
        const float* w = sw0 + (kb) * 16;                         \
        cpa16(dd,          a);                                    \
        cpa16(dd + 4096,   a + (size_t)64 * K);                   \
        cpa16(dd + 8192,   w);                                    \
        cpa16(dd + 12288,  w + (size_t)64 * K);                   \
    }

    float acc[4][4][4];
#pragma unroll
    for (int i = 0; i < 4; i++)
#pragma unroll
        for (int j = 0; j < 4; j++)
#pragma unroll
            for (int l = 0; l < 4; l++) acc[i][j][l] = 0.f;

    GISSUE(0, 0); cpcommit();
    GISSUE(1, 1); cpcommit();
    GISSUE(2, 2); cpcommit();

    for (int kb = 0; kb < NKB; kb++) {
        cpwait<2>();
        __syncthreads();
        if (kb + 3 < NKB) GISSUE(kb + 3, (kb + 3) & 3);
        cpcommit();

        const uint32_t sbk = sbase + (uint32_t)((kb & 3) << 14);
#pragma unroll
        for (int ks = 0; ks < 2; ks++) {
            const uint32_t kx = (uint32_t)(ks << 5);
            uint4 af[4];
#pragma unroll
            for (int mt = 0; mt < 4; mt++)
                af[mt] = ldsm4(sbk + (relA[mt] ^ kx));
            const uint4 bq0 = ldsm4(sbk + (relB[0] ^ kx));
            const uint4 bq1 = ldsm4(sbk + (relB[1] ^ kx));
#pragma unroll
            for (int mt = 0; mt < 4; mt++) {
                mma8(acc[mt][0], af[mt].x, af[mt].y, af[mt].z, af[mt].w, bq0.x, bq0.y);
                mma8(acc[mt][1], af[mt].x, af[mt].y, af[mt].z, af[mt].w, bq0.z, bq0.w);
                mma8(acc[mt][2], af[mt].x, af[mt].y, af[mt].z, af[mt].w, bq1.x, bq1.y);
                mma8(acc[mt][3], af[mt].x, af[mt].y, af[mt].z, af[mt].w, bq1.z, bq1.w);
            }
        }
    }
#undef GISSUE

    // ---- epilogue ----
    const float qs = (MODE == 2 && z == 0) ? 0.125f : 1.0f;
#pragma unroll
    for (int mt = 0; mt < 4; mt++) {
        const int r1 = bm + wm * 64 + mt * 16 + gid;
        const int r2 = r1 + 8;
#pragma unroll
        for (int nt = 0; nt < 4; nt++) {
            const int n = bn + wn * 32 + nt * 8 + 2 * tig;
            const float bx = __ldg(&bias[n]), by = __ldg(&bias[n + 1]);
            if (MODE == 0) {
                *(float2*)&C[(size_t)r1 * N + n] =
                    make_float2(acc[mt][nt][0] + bx, acc[mt][nt][1] + by);
                *(float2*)&C[(size_t)r2 * N + n] =
                    make_float2(acc[mt][nt][2] + bx, acc[mt][nt][3] + by);
            } else {
                float2 v1 = make_float2(rndtf((acc[mt][nt][0] + bx) * qs),
                                        rndtf((acc[mt][nt][1] + by) * qs));
                float2 v2 = make_float2(rndtf((acc[mt][nt][2] + bx) * qs),
                                        rndtf((acc[mt][nt][3] + by) * qs));
                const int hh = n >> 6, ee = n & 63;
                const int b1r = r1 >> 11, s1r = r1 & (S - 1);
                const int b2r = r2 >> 11, s2r = r2 & (S - 1);
                *(float2*)&C[(((size_t)b1r * H + hh) * S + s1r) * HD + ee] = v1;
                *(float2*)&C[(((size_t)b2r * H + hh) * S + s2r) * HD + ee] = v2;
            }
        }
    }
}

// ---------------------------------------------------------------------------
// TF32 flash attention, 128-row Q tiles, 256 threads (8 warps; warp owns 16
// rows — per-warp program identical to R8). cp.async double-buffered K/V.
// Smem bytes: K0 @0, K1 @16384, V0 @32768, V1 @51200, QP @69632 (Q region
// reused for P after Q is hoisted to registers). Total 104448 B, 2 CTAs/SM.
// ---------------------------------------------------------------------------
constexpr uint32_t QP_B = 69632u;
constexpr int      QP_W = 17408;      // word offset of QP region

__global__ __launch_bounds__(256, 2)
void attn_tc(const float* __restrict__ q,
             const float* __restrict__ k,
             const float* __restrict__ v,
             float* __restrict__ out)
{
    extern __shared__ __align__(16) uint32_t sma[];
    const uint32_t sb = (uint32_t)__cvta_generic_to_shared(sma);

    const int t    = threadIdx.x;
    const int lane = t & 31;
    const int warp = t >> 5;          // 0..7
    const int gid  = lane >> 2;
    const int tig  = lane & 3;
    const int rm   = warp * 16;

    const int hb = blockIdx.y, bb = blockIdx.z;
    const int m0 = blockIdx.x * 128;
    const size_t base = ((size_t)bb * H + hb) * S * HD;
    const float* qb  = q + base + (size_t)m0 * HD;
    const float* kb_ = k + base;
    const float* vb_ = v + base;

    const int crow = t >> 4;   // 0..15
    const int cg   = t & 15;

    // ---- issue Q (128 rows, group 0) ----
#pragma unroll
    for (int i = 0; i < 8; i++) {
        const int row = crow + i * 16;
        cpa16(sb + QP_B + row * 256 + (uint32_t)((cg ^ (row & 7)) << 4),
              qb + row * 64 + cg * 4);
    }
    cpcommit();

#define KV_ISSUE(n0, buf)                                                        \
    {                                                                            \
        const float* kp = kb_ + (size_t)(n0) * HD;                               \
        const float* vp = vb_ + (size_t)(n0) * HD;                               \
        _Pragma("unroll")                                                        \
        for (int i = 0; i < 4; i++) {                                            \
            const int row = crow + i * 16;                                       \
            cpa16(sb + (uint32_t)(buf) * 16384u + row * 256 +                    \
                      (uint32_t)((cg ^ (row & 7)) << 4),                         \
                  kp + row * 64 + cg * 4);                                       \
        }                                                                        \
        _Pragma("unroll")                                                        \
        for (int i = 0; i < 4; i++) {                                            \
            const int row = crow + i * 16;                                       \
            cpa16(sb + 32768u + (uint32_t)(buf) * 18432u + row * 288 +           \
                      (uint32_t)(cg << 4),                                       \
                  vp + row * 64 + cg * 4);                                       \
        }                                                                        \
    }

    KV_ISSUE(0, 0);  cpcommit();
    KV_ISSUE(64, 1); cpcommit();

    // ---- fragment addresses ----
    uint32_t relK[4], relQ, relP;
    {
        const int hiB = (lane >> 3) & 1;
#pragma unroll
        for (int n2 = 0; n2 < 4; n2++) {
            const int row = n2 * 16 + (lane & 7) + ((lane >> 1) & 8);
            relK[n2] = row * 256 + (uint32_t)((hiB ^ (row & 7)) << 4);
        }
        const int hiA  = (lane >> 4) & 1;
        const int rowq = rm + (lane & 7) + (lane & 8);
        relQ = QP_B + rowq * 256 + (uint32_t)((hiA ^ (rowq & 7)) << 4);
        relP = QP_B + rowq * 272 + (uint32_t)(hiA << 4);
    }

    cpwait<2>();
    __syncthreads();
    uint4 qf[8];
#pragma unroll
    for (int ks = 0; ks < 8; ks++)
        qf[ks] = ldsm4(sb + (relQ ^ (uint32_t)(ks << 5)));
    __syncthreads();   // Q fully in registers before QP region is reused for P

    float m1 = -1e30f, m2 = -1e30f, l1 = 0.f, l2 = 0.f;
    float o[8][4];
#pragma unroll
    for (int nt = 0; nt < 8; nt++)
#pragma unroll
        for (int j = 0; j < 4; j++) o[nt][j] = 0.f;

    for (int kt = 0; kt < 32; kt++) {
        cpwait<1>();
        __syncthreads();
        const uint32_t kbase = sb + (uint32_t)((kt & 1) << 14);
        const int vw = 8192 + (kt & 1) * 4608;

        // ---- scores = Q . K^T ----
        float sc[8][4];
#pragma unroll
        for (int nt = 0; nt < 8; nt++)
#pragma unroll
            for (int j = 0; j < 4; j++) sc[nt][j] = 0.f;
#pragma unroll
        for (int ks = 0; ks < 8; ks++) {
            const uint32_t kx = (uint32_t)(ks << 5);
#pragma unroll
            for (int n2 = 0; n2 < 4; n2++) {
                const uint4 bf = ldsm4(kbase + (relK[n2] ^ kx));
                mma8(sc[2 * n2],     qf[ks].x, qf[ks].y, qf[ks].z, qf[ks].w, bf.x, bf.y);
                mma8(sc[2 * n2 + 1], qf[ks].x, qf[ks].y, qf[ks].z, qf[ks].w, bf.z, bf.w);
            }
        }

        // ---- online softmax in registers ----
        float mx1 = -1e30f, mx2 = -1e30f;
#pragma unroll
        for (int nt = 0; nt < 8; nt++) {
            mx1 = fmaxf(mx1, fmaxf(sc[nt][0], sc[nt][1]));
            mx2 = fmaxf(mx2, fmaxf(sc[nt][2], sc[nt][3]));
        }
        mx1 = fmaxf(mx1, __shfl_xor_sync(0xffffffffu, mx1, 1));
        mx1 = fmaxf(mx1, __shfl_xor_sync(0xffffffffu, mx1, 2));
        mx2 = fmaxf(mx2, __shfl_xor_sync(0xffffffffu, mx2, 1));
        mx2 = fmaxf(mx2, __shfl_xor_sync(0xffffffffu, mx2, 2));
        const float M1 = fmaxf(m1, mx1);
        const float M2 = fmaxf(m2, mx2);

        float s1 = 0.f, s2 = 0.f;
#pragma unroll
        for (int nt = 0; nt < 8; nt++) {
            sc[nt][0] = __expf(sc[nt][0] - M1); s1 += sc[nt][0];
            sc[nt][1] = __expf(sc[nt][1] - M1); s1 += sc[nt][1];
            sc[nt][2] = __expf(sc[nt][2] - M2); s2 += sc[nt][2];
            sc[nt][3] = __expf(sc[nt][3] - M2); s2 += sc[nt][3];
        }
        s1 += __shfl_xor_sync(0xffffffffu, s1, 1);
        s1 += __shfl_xor_sync(0xffffffffu, s1, 2);
        s2 += __shfl_xor_sync(0xffffffffu, s2, 1);
        s2 += __shfl_xor_sync(0xffffffffu, s2, 2);

        const float c1 = __expf(m1 - M1);
        const float c2 = __expf(m2 - M2);
        l1 = l1 * c1 + s1;
        l2 = l2 * c2 + s2;
        m1 = M1; m2 = M2;
#pragma unroll
        for (int nt = 0; nt < 8; nt++) {
            o[nt][0] *= c1; o[nt][1] *= c1;
            o[nt][2] *= c2; o[nt][3] *= c2;
        }

        // ---- P -> smem (tf32), warp-private rows (stride 68 words) ----
#pragma unroll
        for (int nt = 0; nt < 8; nt++) {
            const int cc = nt * 8 + 2 * tig;
            *(uint2*)&sma[QP_W + (rm + gid) * 68 + cc] =
                make_uint2(f2tf(sc[nt][0]), f2tf(sc[nt][1]));
            *(uint2*)&sma[QP_W + (rm + gid + 8) * 68 + cc] =
                make_uint2(f2tf(sc[nt][2]), f2tf(sc[nt][3]));
        }
        __syncwarp();

        // ---- O += P . V ----
#pragma unroll
        for (int ksp = 0; ksp < 8; ksp++) {
            const uint4 pf = ldsm4(sb + relP + (uint32_t)(ksp * 32));
            const int vrow = vw + (ksp * 8 + tig) * 72;
#pragma unroll
            for (int nt = 0; nt < 8; nt++) {
                const uint32_t vb0 = sma[vrow + nt * 8 + gid];
                const uint32_t vb1 = sma[vrow + 288 + nt * 8 + gid];   // +4 rows
                mma8(o[nt], pf.x, pf.y, pf.z, pf.w, vb0, vb1);
            }
        }

        __syncthreads();
        if (kt + 2 < 32) KV_ISSUE((kt + 2) * 64, kt & 1);
        cpcommit();
    }
#undef KV_ISSUE

    // ---- epilogue: normalize, tf32-round, write concat-head layout ----
    const float i1 = 1.f / l1;
    const float i2 = 1.f / l2;
    const int s1r = m0 + rm + gid;
    const int s2r = s1r + 8;
#pragma unroll
    for (int nt = 0; nt < 8; nt++) {
        const int n = nt * 8 + 2 * tig;
        *(float2*)&out[((size_t)bb * S + s1r) * D + hb * HD + n] =
            make_float2(rndtf(o[nt][0] * i1), rndtf(o[nt][1] * i1));
        *(float2*)&out[((size_t)bb * S + s2r) * D + hb * HD + n] =
            make_float2(rndtf(o[nt][2] * i2), rndtf(o[nt][3] * i2));
    }
}

// ---------------------------------------------------------------------------
// Launch
// ---------------------------------------------------------------------------
extern "C" void kernel_launch(void* const* d_in, const int* in_sizes, int n_in,
                              void* d_out, int out_size)
{
    const float* x  = (const float*)d_in[0];
    const float* Wq = (const float*)d_in[1];
    const float* bq = (const float*)d_in[2];
    const float* Wk = (const float*)d_in[3];
    const float* bk = (const float*)d_in[4];
    const float* Wv = (const float*)d_in[5];
    const float* bv = (const float*)d_in[6];
    const float* Wp = (const float*)d_in[7];
    const float* bp = (const float*)d_in[8];
    float* out = (float*)d_out;

    float *q, *k, *v, *attn, *xt, *wt;
    cudaGetSymbolAddress((void**)&q,    g_q);
    cudaGetSymbolAddress((void**)&k,    g_k);
    cudaGetSymbolAddress((void**)&v,    g_v);
    cudaGetSymbolAddress((void**)&attn, g_attn);
    cudaGetSymbolAddress((void**)&xt,   g_xt);
    cudaGetSymbolAddress((void**)&wt,   g_wt);
    float* wqt = wt;
    float* wkt = wt + (size_t)D * D;
    float* wvt = wt + 2 * (size_t)D * D;
    float* wpt = wt + 3 * (size_t)D * D;

    const int smem_gemm = 4 * 16384;   // 65536
    const int smem_attn = 104448;

    cudaFuncSetAttribute(gemm_tc<2>, cudaFuncAttributeMaxDynamicSharedMemorySize, smem_gemm);
    cudaFuncSetAttribute(gemm_tc<0>, cudaFuncAttributeMaxDynamicSharedMemorySize, smem_gemm);
    cudaFuncSetAttribute(attn_tc,    cudaFuncAttributeMaxDynamicSharedMemorySize, smem_attn);

    tf32_cvt<<<dim3(512, 5), 256>>>(x, Wq, Wk, Wv, Wp, xt, wqt, wkt, wvt, wpt);

    gemm_tc<2><<<dim3(D / 128, M / 128, 3), 256, smem_gemm>>>(
        xt, wqt, bq, wkt, bk, wvt, bv, q, k, v);

    attn_tc<<<dim3(S / 128, H, B), 256, smem_attn>>>(q, k, v, attn);

    gemm_tc<0><<<dim3(D / 128, M / 128), 256, smem_gemm>>>(
        attn, wpt, bp, nullptr, nullptr, nullptr, nullptr, out, nullptr, nullptr);
}